// round 8
// baseline (speedup 1.0000x reference)
#include <cuda_runtime.h>
#include <cuda_fp16.h>
#include <math.h>

#define NN 6000
#define EE 100000

typedef unsigned long long ull;

// ---------------- f32x2 packed-FMA helpers (sm_103a FFMA2) ----------------------
__device__ __forceinline__ void fma2(ull& d, ull a, ull b) {
    asm("fma.rn.f32x2 %0, %1, %2, %0;" : "+l"(d) : "l"(a), "l"(b));
}
__device__ __forceinline__ ull pack2(float lo, float hi) {
    ull r; asm("mov.b64 %0, {%1, %2};" : "=l"(r) : "f"(lo), "f"(hi)); return r;
}
__device__ __forceinline__ float2 unpack2(ull v) {
    float2 r; asm("mov.b64 {%0, %1}, %2;" : "=f"(r.x), "=f"(r.y) : "l"(v)); return r;
}

// ---------------- scratch (device globals; no allocations allowed) -------------
__device__ float  g_W0[2 * NN * 32];   // layer-0 combined basis (x=I shortcut)
__device__ float  g_xA[NN * 64];
__device__ float  g_xB[NN * 64];
__device__ float  g_Wr1[2 * 32 * 64];
__device__ float  g_Wr2[2 * 64 * 64];
__device__ float  g_Wr3[2 * 64 * 32];
__device__ __half g_h[NN * 512];       // GAT projected features (fp16)
__device__ float  g_xg[NN * 512];      // GAT output
__device__ float  g_ab[NN * 256];      // [A | B] for edge MLP
__device__ float  g_asv[NN];
__device__ float  g_adv[NN];
__device__ float  g_ps[32];
__device__ float  g_pd[32];
__device__ float  g_cnt[NN * 2];       // per-relation in-counts (float)
__device__ int    g_deg[NN];
__device__ int    g_rowptr[NN + 1];
__device__ int    g_cursor[NN];
__device__ int    g_csrc[EE];
__device__ int    g_ctype[EE];

// ---------------- prep: zero + all wcomp + projected attention vectors ----------
#define PREP_TOTAL (384000 + 4096 + 8192 + 4096 + 18000 + 2048)

__global__ void prep_kernel(const float* __restrict__ basis0, const float* __restrict__ comp0,
                            const float* __restrict__ basis1, const float* __restrict__ comp1,
                            const float* __restrict__ basis2, const float* __restrict__ comp2,
                            const float* __restrict__ basis3, const float* __restrict__ comp3,
                            const float* __restrict__ gw, const float* __restrict__ a_s,
                            const float* __restrict__ a_d,
                            float* __restrict__ W0, float* __restrict__ Wr1,
                            float* __restrict__ Wr2, float* __restrict__ Wr3,
                            int* __restrict__ deg, float* __restrict__ cnt,
                            float* __restrict__ ps, float* __restrict__ pd) {
    int idx = blockIdx.x * blockDim.x + threadIdx.x;
    if (idx < 384000) {
        int r = idx / 192000, io = idx - r * 192000;
        float s = 0.f;
#pragma unroll
        for (int b = 0; b < 4; b++) s += comp0[r * 4 + b] * basis0[b * 192000 + io];
        W0[idx] = s;
        return;
    }
    idx -= 384000;
    if (idx < 4096) {
        int r = idx / 2048, io = idx - r * 2048;
        float s = 0.f;
#pragma unroll
        for (int b = 0; b < 4; b++) s += comp1[r * 4 + b] * basis1[b * 2048 + io];
        Wr1[idx] = s;
        return;
    }
    idx -= 4096;
    if (idx < 8192) {
        int r = idx / 4096, io = idx - r * 4096;
        float s = 0.f;
#pragma unroll
        for (int b = 0; b < 4; b++) s += comp2[r * 4 + b] * basis2[b * 4096 + io];
        Wr2[idx] = s;
        return;
    }
    idx -= 8192;
    if (idx < 4096) {
        int r = idx / 2048, io = idx - r * 2048;
        float s = 0.f;
#pragma unroll
        for (int b = 0; b < 4; b++) s += comp3[r * 4 + b] * basis3[b * 2048 + io];
        Wr3[idx] = s;
        return;
    }
    idx -= 4096;
    if (idx < 18000) {
        if (idx < 6000) deg[idx] = 0;
        else cnt[idx - 6000] = 0.f;
        return;
    }
    idx -= 18000;
    if (idx < 2048) {
        int w = idx >> 5, lane = idx & 31;
        int i = w & 31;
        const float* a = (w < 32) ? a_s : a_d;
        float s = 0.f;
        for (int c = lane; c < 512; c += 32) s += gw[i * 512 + c] * a[c];
#pragma unroll
        for (int off = 16; off > 0; off >>= 1) s += __shfl_down_sync(0xffffffffu, s, off);
        if (lane == 0) { if (w < 32) ps[i] = s; else pd[i] = s; }
    }
}

// ---------------- CSR build ----------------------------------------------------
__global__ void count_kernel(const int* __restrict__ ei, const int* __restrict__ et,
                             int* deg, float* cnt) {
    int e = blockIdx.x * blockDim.x + threadIdx.x;
    if (e >= EE) return;
    int d = ei[EE + e];
    atomicAdd(&deg[d], 1);
    atomicAdd(&cnt[d * 2 + et[e]], 1.0f);
}

__global__ void scan_kernel(const int* __restrict__ deg, int* rowptr, int* cursor) {
    int t = threadIdx.x;  // 1024
    int base = t * 6;
    int loc[6];
    int sum = 0;
#pragma unroll
    for (int i = 0; i < 6; i++) {
        int idx = base + i;
        int v = (idx < NN) ? deg[idx] : 0;
        loc[i] = sum;
        sum += v;
    }
    int lane = t & 31, w = t >> 5;
    int v = sum;
#pragma unroll
    for (int off = 1; off < 32; off <<= 1) {
        int n = __shfl_up_sync(0xffffffffu, v, off);
        if (lane >= off) v += n;
    }
    __shared__ int wsum[32];
    if (lane == 31) wsum[w] = v;
    __syncthreads();
    if (w == 0) {
        int x = wsum[lane];
#pragma unroll
        for (int off = 1; off < 32; off <<= 1) {
            int n = __shfl_up_sync(0xffffffffu, x, off);
            if (lane >= off) x += n;
        }
        wsum[lane] = x;
    }
    __syncthreads();
    int incl = v + (w > 0 ? wsum[w - 1] : 0);
    int excl = incl - sum;
#pragma unroll
    for (int i = 0; i < 6; i++) {
        int idx = base + i;
        if (idx < NN) { rowptr[idx] = excl + loc[i]; cursor[idx] = excl + loc[i]; }
    }
    if (t == 1023) rowptr[NN] = incl;
}

__global__ void fill_kernel(const int* __restrict__ ei, const int* __restrict__ et,
                            int* cursor, int* csrc, int* ctype) {
    int e = blockIdx.x * blockDim.x + threadIdx.x;
    if (e >= EE) return;
    int s = ei[e];
    int d = ei[EE + e];
    int pos = atomicAdd(&cursor[d], 1);
    csrc[pos] = s;
    ctype[pos] = et[e];
}

// ---------------- layer 0: x = I shortcut --------------------------------------
// x1[n] = tanh(root0[n] + bias + mean_r(W0_r[src]))  (gather over [2NN,32])
__global__ void agg_rgcn0(const float* __restrict__ W0, const float* __restrict__ root0,
                          const float* __restrict__ bias, const float* __restrict__ cnt,
                          const int* __restrict__ rowptr, const int* __restrict__ csrc,
                          const int* __restrict__ ctype,
                          float* __restrict__ xout) {
    int m = threadIdx.y;
    int n = blockIdx.x * blockDim.y + m;
    int o = threadIdx.x;  // 32
    float a0 = 0.f, a1 = 0.f;
    int e0 = rowptr[n], e1 = rowptr[n + 1];
    int e = e0;
    for (; e + 4 <= e1; e += 4) {
        int s0 = csrc[e],  s1 = csrc[e + 1], s2 = csrc[e + 2], s3 = csrc[e + 3];
        int t0 = ctype[e], t1 = ctype[e + 1], t2 = ctype[e + 2], t3 = ctype[e + 3];
        float v0 = W0[(t0 * NN + s0) * 32 + o];
        float v1 = W0[(t1 * NN + s1) * 32 + o];
        float v2 = W0[(t2 * NN + s2) * 32 + o];
        float v3 = W0[(t3 * NN + s3) * 32 + o];
        if (t0) a1 += v0; else a0 += v0;
        if (t1) a1 += v1; else a0 += v1;
        if (t2) a1 += v2; else a0 += v2;
        if (t3) a1 += v3; else a0 += v3;
    }
    for (; e < e1; e++) {
        int s = csrc[e];
        int t = ctype[e];
        float v = W0[(t * NN + s) * 32 + o];
        if (t) a1 += v; else a0 += v;
    }
    float c0 = fmaxf(cnt[n * 2 + 0], 1.f);
    float c1 = fmaxf(cnt[n * 2 + 1], 1.f);
    xout[n * 32 + o] = tanhf(root0[n * 32 + o] + bias[o] + a0 / c0 + a1 / c1);
}

// ---------------- layers 1-3: aggregate-then-transform --------------------------
// Phase 1: mean0/mean1 = per-relation mean of xin[src] (IN dims), xown = xin[n].
// Phase 2: xout[n] = tanh(xown@root + mean0@W0 + mean1@W1 + bias).
template<int IN, int OUT>
__global__ __launch_bounds__(512) void layer_kernel(
    const float* __restrict__ xin, const float* __restrict__ Wr,
    const float* __restrict__ root, const float* __restrict__ bias,
    const float* __restrict__ cnt,
    const int* __restrict__ rowptr, const int* __restrict__ csrc,
    const int* __restrict__ ctype,
    float* __restrict__ xout) {
    constexpr int M = 16;
    __shared__ __align__(16) float m0T[IN][M];
    __shared__ __align__(16) float m1T[IN][M];
    __shared__ __align__(16) float xoT[IN][M];
    __shared__ float wsh[2 * IN * OUT];
    const int tid = threadIdx.x;
    const int n0 = blockIdx.x * M;

    for (int i = tid; i < 2 * IN * OUT; i += 512) wsh[i] = Wr[i];

    // phase 1: col-per-thread aggregation (round-7 proven mapping, unroll-4)
    {
        const int k = tid % IN;
        const int mr = tid / IN;
        constexpr int NP = 512 / IN;
#pragma unroll
        for (int m = mr; m < M; m += NP) {
            int n = n0 + m;
            float a0 = 0.f, a1 = 0.f;
            int e0 = rowptr[n], e1 = rowptr[n + 1];
            int e = e0;
            for (; e + 4 <= e1; e += 4) {
                int s0 = csrc[e],  s1 = csrc[e + 1], s2 = csrc[e + 2], s3 = csrc[e + 3];
                int t0 = ctype[e], t1 = ctype[e + 1], t2 = ctype[e + 2], t3 = ctype[e + 3];
                float v0 = xin[s0 * IN + k];
                float v1 = xin[s1 * IN + k];
                float v2 = xin[s2 * IN + k];
                float v3 = xin[s3 * IN + k];
                if (t0) a1 += v0; else a0 += v0;
                if (t1) a1 += v1; else a0 += v1;
                if (t2) a1 += v2; else a0 += v2;
                if (t3) a1 += v3; else a0 += v3;
            }
            for (; e < e1; e++) {
                int s = csrc[e];
                float v = xin[s * IN + k];
                if (ctype[e]) a1 += v; else a0 += v;
            }
            m0T[k][m] = a0 / fmaxf(cnt[n * 2 + 0], 1.f);
            m1T[k][m] = a1 / fmaxf(cnt[n * 2 + 1], 1.f);
            xoT[k][m] = xin[n * IN + k];
        }
    }
    __syncthreads();

    // phase 2: in-shared GEMM + tanh
    constexpr int G = 512 / OUT;
    const int o = tid % OUT;
    const int g = tid / OUT;
    if constexpr (M / G == 2) {
        // pair mode (OUT=64): thread handles nodes {2g, 2g+1}
        ull ac0 = 0, ac1 = 0, ac2 = 0;
        for (int i = 0; i < IN; i++) {
            float w0 = wsh[i * OUT + o];
            float w1 = wsh[IN * OUT + i * OUT + o];
            float wr = __ldg(&root[i * OUT + o]);
            fma2(ac0, *(const ull*)&m0T[i][2 * g], pack2(w0, w0));
            fma2(ac1, *(const ull*)&m1T[i][2 * g], pack2(w1, w1));
            fma2(ac2, *(const ull*)&xoT[i][2 * g], pack2(wr, wr));
        }
        float2 v0 = unpack2(ac0), v1 = unpack2(ac1), v2 = unpack2(ac2);
        float bo = bias[o];
        int n = n0 + 2 * g;
        xout[n * OUT + o]       = tanhf(v0.x + v1.x + v2.x + bo);
        xout[(n + 1) * OUT + o] = tanhf(v0.y + v1.y + v2.y + bo);
    } else {
        // scalar mode (OUT=32): one (node, col) per thread
        float ac0 = 0.f, ac1 = 0.f, ac2 = 0.f;
        for (int i = 0; i < IN; i++) {
            ac0 += m0T[i][g] * wsh[i * OUT + o];
            ac1 += m1T[i][g] * wsh[IN * OUT + i * OUT + o];
            ac2 += xoT[i][g] * __ldg(&root[i * OUT + o]);
        }
        xout[(n0 + g) * OUT + o] = tanhf(ac0 + ac1 + ac2 + bias[o]);
    }
}

// ---------------- GAT ----------------------------------------------------------
__device__ __forceinline__ float lrelu02(float a) { return a > 0.f ? a : 0.2f * a; }

__global__ __launch_bounds__(512) void gat_h_kernel(const float* __restrict__ x,
                                                    const float* __restrict__ gw,
                                                    const float* __restrict__ ps,
                                                    const float* __restrict__ pd,
                                                    __half* __restrict__ h,
                                                    float* __restrict__ asv, float* __restrict__ adv) {
    __shared__ float xsT[32][40];
    const int c = threadIdx.x;
    const int n0 = blockIdx.x * 40;
    for (int i = c; i < 40 * 32; i += 512) {
        int m = i >> 5, k = i & 31;
        xsT[k][m] = x[(n0 + m) * 32 + k];
    }
    __syncthreads();
    ull gwd[32];
#pragma unroll
    for (int k = 0; k < 32; k++) {
        float g = gw[k * 512 + c];
        gwd[k] = pack2(g, g);
    }
#pragma unroll 4
    for (int mp = 0; mp < 20; mp++) {
        ull acc = 0;
#pragma unroll
        for (int k = 0; k < 32; k++) {
            ull xp = *(const ull*)&xsT[k][2 * mp];
            fma2(acc, xp, gwd[k]);
        }
        float2 v = unpack2(acc);
        h[(size_t)(n0 + 2 * mp) * 512 + c] = __float2half(v.x);
        h[(size_t)(n0 + 2 * mp + 1) * 512 + c] = __float2half(v.y);
    }
    if (c < 40) {
        float s = 0.f, t = 0.f;
#pragma unroll
        for (int k = 0; k < 32; k++) {
            float xv = xsT[k][c];
            s += xv * __ldg(&ps[k]);
            t += xv * __ldg(&pd[k]);
        }
        asv[n0 + c] = s;
        adv[n0 + c] = t;
    }
}

__global__ void gat_agg_kernel(const __half* __restrict__ h, const float* __restrict__ asv,
                               const float* __restrict__ adv,
                               const int* __restrict__ rowptr, const int* __restrict__ csrc,
                               const float* __restrict__ gbias, float* __restrict__ xout) {
    int n = blockIdx.x;
    int t = threadIdx.x;  // 128 threads, 4 fp16 features each
    int e0 = rowptr[n], e1 = rowptr[n + 1];
    float advn = adv[n];
    float aself = lrelu02(asv[n] + advn);
    float lm = aself;
    for (int e = e0 + t; e < e1; e += 128) lm = fmaxf(lm, lrelu02(asv[csrc[e]] + advn));
    __shared__ float sred[128];
    sred[t] = lm;
    __syncthreads();
    for (int off = 64; off > 0; off >>= 1) {
        if (t < off) sred[t] = fmaxf(sred[t], sred[t + off]);
        __syncthreads();
    }
    float m = sred[0];
    __shared__ float sEx[128];
    __shared__ int sSrc[128];
    float4 acc = make_float4(0.f, 0.f, 0.f, 0.f);
    float denom = 0.f;
    for (int eb = e0; eb < e1; eb += 128) {
        int cnt = min(128, e1 - eb);
        __syncthreads();
        if (t < cnt) {
            int s = csrc[eb + t];
            sSrc[t] = s;
            sEx[t] = expf(lrelu02(asv[s] + advn) - m);
        }
        __syncthreads();
        for (int j = 0; j < cnt; j++) {
            float ex = sEx[j];
            uint2 raw = reinterpret_cast<const uint2*>(h + (size_t)sSrc[j] * 512)[t];
            float2 f0 = __half22float2(*reinterpret_cast<__half2*>(&raw.x));
            float2 f1 = __half22float2(*reinterpret_cast<__half2*>(&raw.y));
            acc.x += ex * f0.x; acc.y += ex * f0.y; acc.z += ex * f1.x; acc.w += ex * f1.y;
            denom += ex;
        }
    }
    float exs = expf(aself - m);
    denom += exs;
    {
        uint2 raw = reinterpret_cast<const uint2*>(h + (size_t)n * 512)[t];
        float2 f0 = __half22float2(*reinterpret_cast<__half2*>(&raw.x));
        float2 f1 = __half22float2(*reinterpret_cast<__half2*>(&raw.y));
        acc.x += exs * f0.x; acc.y += exs * f0.y; acc.z += exs * f1.x; acc.w += exs * f1.y;
    }
    float inv = 1.f / fmaxf(denom, 1e-16f);
    float4 g = reinterpret_cast<const float4*>(gbias)[t];
    float4 o;
    o.x = fmaxf(acc.x * inv + g.x, 0.f);
    o.y = fmaxf(acc.y * inv + g.y, 0.f);
    o.z = fmaxf(acc.z * inv + g.z, 0.f);
    o.w = fmaxf(acc.w * inv + g.w, 0.f);
    reinterpret_cast<float4*>(xout + (size_t)n * 512)[t] = o;
}

// ---------------- edge MLP ------------------------------------------------------
__global__ __launch_bounds__(256) void gemm_ab_kernel(const float* __restrict__ xg,
                                                      const float* __restrict__ w1,
                                                      float* __restrict__ ab) {
    __shared__ float xsT[32][40];
    __shared__ float ws[32][256];
    const int c = threadIdx.x;
    const int n0 = blockIdx.x * 40;
    ull acc[20];
#pragma unroll
    for (int p = 0; p < 20; p++) acc[p] = 0;
    for (int k0 = 0; k0 < 512; k0 += 32) {
        __syncthreads();
        for (int i = c; i < 40 * 32; i += 256) {
            int m = i >> 5, kk = i & 31;
            xsT[kk][m] = xg[(size_t)(n0 + m) * 512 + k0 + kk];
        }
        for (int i = c; i < 32 * 256; i += 256) {
            int kk = i >> 8, cc = i & 255;
            int krow = k0 + kk + ((cc < 128) ? 0 : 512);
            int col = cc & 127;
            ws[kk][cc] = w1[krow * 128 + col];
        }
        __syncthreads();
#pragma unroll 8
        for (int kk = 0; kk < 32; kk++) {
            float wv = ws[kk][c];
            ull wd = pack2(wv, wv);
            const float* xr = &xsT[kk][0];
#pragma unroll
            for (int p = 0; p < 20; p++) {
                ull xp = *(const ull*)(xr + 2 * p);
                fma2(acc[p], xp, wd);
            }
        }
    }
#pragma unroll
    for (int p = 0; p < 20; p++) {
        float2 v = unpack2(acc[p]);
        ab[(size_t)(n0 + 2 * p) * 256 + c] = v.x;
        ab[(size_t)(n0 + 2 * p + 1) * 256 + c] = v.y;
    }
}

__global__ void edge_kernel(const int* __restrict__ ei, const float* __restrict__ ab,
                            const float* __restrict__ b1, const float* __restrict__ w2,
                            const float* __restrict__ b2, float* __restrict__ out) {
    int gid = blockIdx.x * blockDim.x + threadIdx.x;
    int e = gid >> 5;
    int lane = gid & 31;
    if (e >= EE) return;
    int s = ei[e];
    int d = ei[EE + e];
    float4 a = reinterpret_cast<const float4*>(ab + (size_t)s * 256)[lane];
    float4 bv = reinterpret_cast<const float4*>(ab + (size_t)d * 256 + 128)[lane];
    float4 bb = reinterpret_cast<const float4*>(b1)[lane];
    float4 wv = reinterpret_cast<const float4*>(w2)[lane];
    float acc = fmaxf(a.x + bv.x + bb.x, 0.f) * wv.x
              + fmaxf(a.y + bv.y + bb.y, 0.f) * wv.y
              + fmaxf(a.z + bv.z + bb.z, 0.f) * wv.z
              + fmaxf(a.w + bv.w + bb.w, 0.f) * wv.w;
#pragma unroll
    for (int off = 16; off > 0; off >>= 1) acc += __shfl_down_sync(0xffffffffu, acc, off);
    if (lane == 0) out[e] = 1.f / (1.f + expf(-(acc + b2[0])));
}

// ---------------- launch ---------------------------------------------------------
extern "C" void kernel_launch(void* const* d_in, const int* in_sizes, int n_in,
                              void* d_out, int out_size) {
    const float *basis[4], *comp[4], *root[4], *rbias[4];
    const float *gat_w, *att_s, *att_d, *gat_b, *w1, *b1, *w2, *b2;
    const int *ei, *et;

    if (in_sizes[0] == 2 * EE) {
        ei = (const int*)d_in[0];
        et = (const int*)d_in[1];
        int k = 2;
        for (int l = 0; l < 4; l++) {
            basis[l] = (const float*)d_in[k++];
            comp[l]  = (const float*)d_in[k++];
            root[l]  = (const float*)d_in[k++];
            rbias[l] = (const float*)d_in[k++];
        }
        gat_w = (const float*)d_in[18]; att_s = (const float*)d_in[19];
        att_d = (const float*)d_in[20]; gat_b = (const float*)d_in[21];
        w1 = (const float*)d_in[22]; b1 = (const float*)d_in[23];
        w2 = (const float*)d_in[24]; b2 = (const float*)d_in[25];
    } else if (in_sizes[0] == 4 * NN * 32) {
        int k = 0;
        for (int l = 0; l < 4; l++) {
            basis[l] = (const float*)d_in[k++];
            comp[l]  = (const float*)d_in[k++];
            root[l]  = (const float*)d_in[k++];
            rbias[l] = (const float*)d_in[k++];
        }
        gat_w = (const float*)d_in[16]; att_s = (const float*)d_in[17];
        att_d = (const float*)d_in[18]; gat_b = (const float*)d_in[19];
        w1 = (const float*)d_in[20]; b1 = (const float*)d_in[21];
        w2 = (const float*)d_in[22]; b2 = (const float*)d_in[23];
        ei = (const int*)d_in[24]; et = (const int*)d_in[25];
    } else {
        b1 = (const float*)d_in[0]; b2 = (const float*)d_in[1];
        for (int l = 0; l < 4; l++) basis[l] = (const float*)d_in[2 + l];
        for (int l = 0; l < 4; l++) comp[l] = (const float*)d_in[6 + l];
        ei = (const int*)d_in[10]; et = (const int*)d_in[11];
        att_d = (const float*)d_in[12]; att_s = (const float*)d_in[13];
        gat_b = (const float*)d_in[14]; gat_w = (const float*)d_in[15];
        for (int l = 0; l < 4; l++) rbias[l] = (const float*)d_in[16 + l];
        for (int l = 0; l < 4; l++) root[l] = (const float*)d_in[20 + l];
        w1 = (const float*)d_in[24]; w2 = (const float*)d_in[25];
    }

    float *W0, *xA, *xB, *Wr1, *Wr2, *Wr3, *xg, *ab, *asv, *adv, *cnt, *ps, *pd;
    __half *h;
    int *deg, *rowptr, *cursor, *csrc, *ctype;
    cudaGetSymbolAddress((void**)&W0, g_W0);
    cudaGetSymbolAddress((void**)&xA, g_xA);
    cudaGetSymbolAddress((void**)&xB, g_xB);
    cudaGetSymbolAddress((void**)&Wr1, g_Wr1);
    cudaGetSymbolAddress((void**)&Wr2, g_Wr2);
    cudaGetSymbolAddress((void**)&Wr3, g_Wr3);
    cudaGetSymbolAddress((void**)&h, g_h);
    cudaGetSymbolAddress((void**)&xg, g_xg);
    cudaGetSymbolAddress((void**)&ab, g_ab);
    cudaGetSymbolAddress((void**)&asv, g_asv);
    cudaGetSymbolAddress((void**)&adv, g_adv);
    cudaGetSymbolAddress((void**)&ps, g_ps);
    cudaGetSymbolAddress((void**)&pd, g_pd);
    cudaGetSymbolAddress((void**)&cnt, g_cnt);
    cudaGetSymbolAddress((void**)&deg, g_deg);
    cudaGetSymbolAddress((void**)&rowptr, g_rowptr);
    cudaGetSymbolAddress((void**)&cursor, g_cursor);
    cudaGetSymbolAddress((void**)&csrc, g_csrc);
    cudaGetSymbolAddress((void**)&ctype, g_ctype);

    float* out = (float*)d_out;

    // ---- fused prep (zero + all basis combinations + p_s/p_d) ----
    prep_kernel<<<(PREP_TOTAL + 255) / 256, 256>>>(
        basis[0], comp[0], basis[1], comp[1], basis[2], comp[2], basis[3], comp[3],
        gat_w, att_s, att_d, W0, Wr1, Wr2, Wr3, deg, cnt, ps, pd);

    // ---- CSR build ----
    count_kernel<<<(EE + 255) / 256, 256>>>(ei, et, deg, cnt);
    scan_kernel<<<1, 1024>>>(deg, rowptr, cursor);
    fill_kernel<<<(EE + 255) / 256, 256>>>(ei, et, cursor, csrc, ctype);

    // ---- Layer 0 (x = I shortcut) ----
    agg_rgcn0<<<NN / 8, dim3(32, 8)>>>(W0, root[0], rbias[0], cnt, rowptr, csrc, ctype, xA);

    // ---- Layers 1-3: aggregate-then-transform (one kernel each) ----
    layer_kernel<32, 64><<<NN / 16, 512>>>(xA, Wr1, root[1], rbias[1], cnt,
                                           rowptr, csrc, ctype, xB);
    layer_kernel<64, 64><<<NN / 16, 512>>>(xB, Wr2, root[2], rbias[2], cnt,
                                           rowptr, csrc, ctype, xA);
    layer_kernel<64, 32><<<NN / 16, 512>>>(xA, Wr3, root[3], rbias[3], cnt,
                                           rowptr, csrc, ctype, xB);

    // ---- GAT ----
    gat_h_kernel<<<NN / 40, 512>>>(xB, gat_w, ps, pd, h, asv, adv);
    gat_agg_kernel<<<NN, 128>>>(h, asv, adv, rowptr, csrc, gat_b, xg);

    // ---- edge MLP (factorized: feat@w1 = A[src]+B[dst]) ----
    gemm_ab_kernel<<<NN / 40, 256>>>(xg, w1, ab);
    edge_kernel<<<(EE * 32 + 255) / 256, 256>>>(ei, ab, b1, w2, b2, out);
}